// round 14
// baseline (speedup 1.0000x reference)
#include <cuda_runtime.h>
#include <cuda_bf16.h>
#include <cstdint>

#define BSZ 512
#define DIM 128
#define NCLS 64
#define MARGIN 0.2f

// Scratch (no allocations anywhere)
__device__ float g_dist[BSZ * BSZ];
__device__ float g_psum[NCLS];
__device__ int   g_pcnt[NCLS];
__device__ int   g_ctr;       // zero-init; last block resets -> replay-safe

typedef unsigned long long ull;

// ---- packed f32x2 helpers (Blackwell) -------------------------------------
__device__ __forceinline__ ull add2(ull a, ull b) {
    ull r; asm("add.rn.f32x2 %0, %1, %2;" : "=l"(r) : "l"(a), "l"(b)); return r;
}
__device__ __forceinline__ ull fma2(ull a, ull b, ull c) {
    ull r; asm("fma.rn.f32x2 %0, %1, %2, %3;" : "=l"(r) : "l"(a), "l"(b), "l"(c)); return r;
}
__device__ __forceinline__ float sum2(ull v) {
    float lo, hi;
    asm("mov.b64 {%0, %1}, %2;" : "=f"(lo), "=f"(hi) : "l"(v));
    return lo + hi;
}

// ---------------------------------------------------------------------------
// Kernel A: pairwise Euclidean dist, diff-based (reference sum((a-b)^2)),
// packed f32x2 (sub == add of negated B). 32x32 tile, 2x2 micro. (R3 version,
// measured ~5.5us.)
// ---------------------------------------------------------------------------
__global__ __launch_bounds__(256, 4)
void dist_kernel(const float* __restrict__ emb) {
    __shared__ float sA[32][130];
    __shared__ float sB[32][130];   // NEGATED B rows

    const int tx = threadIdx.x, ty = threadIdx.y;
    const int tid = ty * 16 + tx;
    const int i0 = blockIdx.y * 32;
    const int j0 = blockIdx.x * 32;

    #pragma unroll
    for (int t = tid; t < 1024; t += 256) {
        const int row = t >> 5;
        const int c4  = t & 31;
        const float4 va = *(const float4*)(emb + (size_t)(i0 + row) * DIM + c4 * 4);
        float2* da = (float2*)&sA[row][c4 * 4];
        da[0] = make_float2(va.x, va.y);
        da[1] = make_float2(va.z, va.w);
        const float4 vb = *(const float4*)(emb + (size_t)(j0 + row) * DIM + c4 * 4);
        float2* db = (float2*)&sB[row][c4 * 4];
        db[0] = make_float2(-vb.x, -vb.y);
        db[1] = make_float2(-vb.z, -vb.w);
    }
    __syncthreads();

    const ull* A0 = (const ull*)sA[ty * 2 + 0];
    const ull* A1 = (const ull*)sA[ty * 2 + 1];
    const ull* B0 = (const ull*)sB[tx * 2 + 0];
    const ull* B1 = (const ull*)sB[tx * 2 + 1];

    ull acc00 = 0ull, acc01 = 0ull, acc10 = 0ull, acc11 = 0ull;

    #pragma unroll 16
    for (int k2 = 0; k2 < 64; k2++) {
        const ull a0 = A0[k2];
        const ull a1 = A1[k2];
        const ull b0 = B0[k2];
        const ull b1 = B1[k2];
        ull t;
        t = add2(a0, b0); acc00 = fma2(t, t, acc00);
        t = add2(a0, b1); acc01 = fma2(t, t, acc01);
        t = add2(a1, b0); acc10 = fma2(t, t, acc10);
        t = add2(a1, b1); acc11 = fma2(t, t, acc11);
    }

    const int i = i0 + ty * 2;
    const int j = j0 + tx * 2;
    const float s00 = sum2(acc00), s01 = sum2(acc01);
    const float s10 = sum2(acc10), s11 = sum2(acc11);
    g_dist[(size_t)(i + 0) * BSZ + (j + 0)] = s00 > 0.f ? sqrtf(s00) : 0.f;
    g_dist[(size_t)(i + 0) * BSZ + (j + 1)] = s01 > 0.f ? sqrtf(s01) : 0.f;
    g_dist[(size_t)(i + 1) * BSZ + (j + 0)] = s10 > 0.f ? sqrtf(s10) : 0.f;
    g_dist[(size_t)(i + 1) * BSZ + (j + 1)] = s11 > 0.f ? sqrtf(s11) : 0.f;
}

// ---------------------------------------------------------------------------
// Kernel B: class-parallel mining. Block c handles class c:
//  - per-class neg masks / neg-rank prefix / j0 / ordered member list (once)
//  - ONE THREAD PER VALID PAIR (i<p, both class c):
//      j_min = first j: neg[j] && d_ap < d[i,j] < d_ap+margin (batch-4 LDG)
//      found  -> d_an = d[i, negrank(j_min)]   (reference quirk)
//      !found -> d_an = d[i, j0]               (j0 = first negative, else 0)
//      loss  += relu(d_ap^2 - d_an^2 + margin)
//  - fixed-order reductions everywhere -> deterministic.
// ---------------------------------------------------------------------------
__global__ __launch_bounds__(256, 4)
void mine_kernel(const int* __restrict__ labels, float* __restrict__ out) {
    __shared__ int      slab[BSZ];
    __shared__ unsigned negw[16];
    __shared__ int      base[16];     // member-list write base per word
    __shared__ int      nrkb[16];     // exclusive prefix of neg counts
    __shared__ int      mlist[BSZ];   // ordered class members
    __shared__ float    partial[256];
    __shared__ int      sK, sJ0, sLast;

    const int c    = blockIdx.x;      // class id
    const int tid  = threadIdx.x;
    const int warp = tid >> 5;
    const int lane = tid & 31;

    slab[tid]       = labels[tid];
    slab[tid + 256] = labels[tid + 256];
    partial[tid]    = 0.f;
    __syncthreads();

    // per-warp: words 2w and 2w+1 (warp w covers labels [64w, 64w+64))
    unsigned mw[2];
    #pragma unroll
    for (int h = 0; h < 2; h++) {
        const int j = warp * 64 + h * 32 + lane;
        const unsigned m = __ballot_sync(0xffffffffu, slab[j] == c);
        mw[h] = m;
        if (lane == 0) negw[warp * 2 + h] = ~m;
    }
    __syncthreads();

    // thread 0: serial prefixes over 16 words (trivial)
    if (tid == 0) {
        int mb = 0, nb = 0, jj0 = 0, found = 0;
        #pragma unroll
        for (int q = 0; q < 16; q++) {
            const unsigned nwv = negw[q];
            base[q] = mb;
            nrkb[q] = nb;
            mb += __popc(~nwv);          // match count
            nb += __popc(nwv);           // neg count
            if (!found && nwv) { jj0 = q * 32 + (__ffs(nwv) - 1); found = 1; }
        }
        sK  = mb;
        sJ0 = jj0;                       // argmax(all-false) == 0 default
    }
    __syncthreads();

    // ordered member list
    #pragma unroll
    for (int h = 0; h < 2; h++) {
        const unsigned m = mw[h];
        if ((m >> lane) & 1u) {
            const int pos = base[warp * 2 + h] + __popc(m & ((1u << lane) - 1u));
            mlist[pos] = warp * 64 + h * 32 + lane;
        }
    }
    __syncthreads();

    const int k = sK;
    const int npairs = k * (k - 1) / 2;
    const int j0 = sJ0;

    float acc = 0.f;
    for (int t = tid; t < npairs; t += 256) {
        // map t -> (a, b), a < b, over k members
        int e = t, a = 0;
        while (e >= k - 1 - a) { e -= (k - 1 - a); a++; }
        const int b = a + 1 + e;
        const int i = mlist[a];
        const int p = mlist[b];

        const float* drow = g_dist + (size_t)i * BSZ;
        const float dap = __ldg(drow + p);
        const float hi  = dap + MARGIN;

        // first j (index order): neg[j] && dap < d[i,j] < hi. Batch-4 LDG.
        int jmin = -1;
        for (int w2 = 0; w2 < 16 && jmin < 0; w2++) {
            unsigned bits = negw[w2];
            while (bits && jmin < 0) {
                int   jj[4];
                float dd[4];
                int   n = 0;
                #pragma unroll
                for (int x = 0; x < 4; x++) {
                    if (bits) {
                        const int bb = __ffs(bits) - 1;
                        bits &= bits - 1;
                        jj[n] = w2 * 32 + bb;
                        dd[n] = __ldg(drow + jj[n]);
                        n++;
                    }
                }
                #pragma unroll
                for (int x = 0; x < 4; x++)
                    if (x < n && jmin < 0 && dd[x] > dap && dd[x] < hi)
                        jmin = jj[x];
            }
        }

        float dan;
        if (jmin >= 0) {
            const int mc = jmin >> 5, mb2 = jmin & 31;
            const int r = nrkb[mc] + __popc(negw[mc] & ((1u << mb2) - 1u));
            dan = __ldg(drow + r);        // reference quirk: index by neg-rank
        } else {
            dan = __ldg(drow + j0);
        }
        const float v = fmaf(dap, dap, MARGIN) - dan * dan;
        acc += v > 0.f ? v : 0.f;
    }
    partial[tid] = acc;
    __syncthreads();

    // fixed-order block tree reduction
    #pragma unroll
    for (int s = 128; s > 0; s >>= 1) {
        if (tid < s) partial[tid] += partial[tid + s];
        __syncthreads();
    }

    if (tid == 0) {
        g_psum[c] = partial[0];
        g_pcnt[c] = npairs;
        __threadfence();
        const int prev = atomicAdd(&g_ctr, 1);
        sLast = (prev == NCLS - 1) ? 1 : 0;
    }
    __syncthreads();

    // last block: deterministic final reduction over 64 class partials
    if (sLast) {
        __threadfence();
        if (tid == 0) {
            float s = 0.f;
            int   n = 0;
            #pragma unroll
            for (int q = 0; q < NCLS; q++) { s += g_psum[q]; n += g_pcnt[q]; }
            out[0] = s / (float)n;
            g_ctr  = 0;                   // reset for next graph replay
        }
    }
}

// ---------------------------------------------------------------------------
extern "C" void kernel_launch(void* const* d_in, const int* in_sizes, int n_in,
                              void* d_out, int out_size) {
    const float* emb    = (const float*)d_in[0];
    const int*   labels = (const int*)d_in[1];
    float*       out    = (float*)d_out;

    dim3 gA(16, 16), bA(16, 16);
    dist_kernel<<<gA, bA>>>(emb);
    mine_kernel<<<NCLS, 256>>>(labels, out);
}

// round 15
// speedup vs baseline: 2.4408x; 2.4408x over previous
#include <cuda_runtime.h>
#include <cuda_bf16.h>
#include <cstdint>

#define BSZ 512
#define DIM 128
#define NCLS 64
#define MARGIN 0.2f
#define PAIR_CAP 131072        // >= C(512,2); safe for any labels
#define MBLK 256               // mine grid blocks

// Scratch (no allocations anywhere)
__device__ float    g_dist[BSZ * BSZ];
__device__ unsigned g_negw[NCLS * 16];     // per-class negative bitmasks
__device__ int      g_nrkb[NCLS * 16];     // per-class neg-count exclusive prefix per word
__device__ int      g_j0[NCLS];            // per-class first-negative index (0 if none)
__device__ int      g_npairs;              // total valid pairs
__device__ unsigned g_pairs[PAIR_CAP];     // packed (i | p<<9 | c<<18)
__device__ float    g_pairval[PAIR_CAP];   // per-pair loss values
__device__ int      g_ctr;                 // zero-init; last block resets -> replay-safe

typedef unsigned long long ull;

// ---- packed f32x2 helpers (Blackwell) -------------------------------------
__device__ __forceinline__ ull add2(ull a, ull b) {
    ull r; asm("add.rn.f32x2 %0, %1, %2;" : "=l"(r) : "l"(a), "l"(b)); return r;
}
__device__ __forceinline__ ull fma2(ull a, ull b, ull c) {
    ull r; asm("fma.rn.f32x2 %0, %1, %2, %3;" : "=l"(r) : "l"(a), "l"(b), "l"(c)); return r;
}
__device__ __forceinline__ float sum2(ull v) {
    float lo, hi;
    asm("mov.b64 {%0, %1}, %2;" : "=f"(lo), "=f"(hi) : "l"(v));
    return lo + hi;
}

// ---------------------------------------------------------------------------
// Kernel 1: 256 blocks do the 32x32-tiled f32x2 distance matrix (proven
// rel_err 1.66e-7); block 256 concurrently precomputes the label-only tables
// (neg masks, neg-rank prefixes, j0, ordered member lists -> packed pair list).
// ---------------------------------------------------------------------------
__global__ __launch_bounds__(256, 4)
void dist_pre_kernel(const float* __restrict__ emb,
                     const int* __restrict__ labels) {
    __shared__ float sA[32][130];
    __shared__ float sB[32][130];   // NEGATED B rows (dist) / aliased scratch (pre)

    const int tid = threadIdx.x;

    if (blockIdx.x == 256) {
        // ---------------- precompute branch (labels only) ----------------
        int*      slab   = (int*)sB;                  // 512 ints
        unsigned* sNegw  = (unsigned*)sB + 512;       // 1024 words
        int*      kcount = (int*)sA;                  // 64
        int*      membase = kcount + 64;              // 64
        int*      pairbase = membase + 64;            // 64
        int*      sMlist = pairbase + 64;             // 512

        slab[tid]       = labels[tid];
        slab[tid + 256] = labels[tid + 256];
        __syncthreads();

        // build 64x16 negative-mask words; thread owns 4 words
        #pragma unroll
        for (int mi = 0; mi < 4; mi++) {
            const int m = tid * 4 + mi;
            const int c = m >> 4, q = m & 15;
            unsigned bits = 0;
            for (int l0 = 0; l0 < 32; l0++) {
                const int l = (l0 + tid) & 31;        // stagger banks
                if (slab[q * 32 + l] == c) bits |= 1u << l;
            }
            const unsigned nw = ~bits;
            sNegw[m]  = nw;
            g_negw[m] = nw;
        }
        __syncthreads();

        // per-class prefixes, j0, member count
        if (tid < NCLS) {
            const int c = tid;
            int nb = 0, kc = 0, j0 = 0, f = 0;
            #pragma unroll
            for (int q = 0; q < 16; q++) {
                const unsigned nw = sNegw[c * 16 + q];
                g_nrkb[c * 16 + q] = nb;
                nb += __popc(nw);
                kc += __popc(~nw);
                if (!f && nw) { j0 = q * 32 + __ffs(nw) - 1; f = 1; }
            }
            kcount[c] = kc;
            g_j0[c]   = j0;                            // argmax(all-false)==0
        }
        __syncthreads();

        if (tid == 0) {
            int mb = 0, pb = 0;
            for (int c = 0; c < NCLS; c++) {
                membase[c]  = mb;
                pairbase[c] = pb;
                const int k = kcount[c];
                mb += k;
                pb += k * (k - 1) / 2;
            }
            g_npairs = pb;
        }
        __syncthreads();

        // member lists + pair list (deterministic order)
        if (tid < NCLS) {
            const int c = tid;
            int mb = membase[c];
            #pragma unroll
            for (int q = 0; q < 16; q++) {
                unsigned mt = ~sNegw[c * 16 + q];
                while (mt) {
                    const int b = __ffs(mt) - 1;
                    mt &= mt - 1;
                    sMlist[mb++] = q * 32 + b;
                }
            }
            const int k = kcount[c], s = membase[c];
            int off = pairbase[c];
            for (int a2 = 0; a2 < k; a2++) {
                const unsigned iv = (unsigned)sMlist[s + a2];
                for (int b2 = a2 + 1; b2 < k; b2++) {
                    g_pairs[off++] = iv | ((unsigned)sMlist[s + b2] << 9)
                                        | ((unsigned)c << 18);
                }
            }
        }
        return;
    }

    // ---------------- dist branch: 32x32 tile, 2x2 micro, f32x2 ----------
    const int tx = tid & 15, ty = tid >> 4;
    const int i0 = (blockIdx.x >> 4) * 32;
    const int j0 = (blockIdx.x & 15) * 32;

    #pragma unroll
    for (int t = tid; t < 1024; t += 256) {
        const int row = t >> 5;
        const int c4  = t & 31;
        const float4 va = *(const float4*)(emb + (size_t)(i0 + row) * DIM + c4 * 4);
        float2* da = (float2*)&sA[row][c4 * 4];
        da[0] = make_float2(va.x, va.y);
        da[1] = make_float2(va.z, va.w);
        const float4 vb = *(const float4*)(emb + (size_t)(j0 + row) * DIM + c4 * 4);
        float2* db = (float2*)&sB[row][c4 * 4];
        db[0] = make_float2(-vb.x, -vb.y);
        db[1] = make_float2(-vb.z, -vb.w);
    }
    __syncthreads();

    const ull* A0 = (const ull*)sA[ty * 2 + 0];
    const ull* A1 = (const ull*)sA[ty * 2 + 1];
    const ull* B0 = (const ull*)sB[tx * 2 + 0];
    const ull* B1 = (const ull*)sB[tx * 2 + 1];

    ull acc00 = 0ull, acc01 = 0ull, acc10 = 0ull, acc11 = 0ull;

    #pragma unroll 16
    for (int k2 = 0; k2 < 64; k2++) {
        const ull a0 = A0[k2];
        const ull a1 = A1[k2];
        const ull b0 = B0[k2];
        const ull b1 = B1[k2];
        ull t;
        t = add2(a0, b0); acc00 = fma2(t, t, acc00);
        t = add2(a0, b1); acc01 = fma2(t, t, acc01);
        t = add2(a1, b0); acc10 = fma2(t, t, acc10);
        t = add2(a1, b1); acc11 = fma2(t, t, acc11);
    }

    const int i = i0 + ty * 2;
    const int j = j0 + tx * 2;
    const float s00 = sum2(acc00), s01 = sum2(acc01);
    const float s10 = sum2(acc10), s11 = sum2(acc11);
    g_dist[(size_t)(i + 0) * BSZ + (j + 0)] = s00 > 0.f ? sqrtf(s00) : 0.f;
    g_dist[(size_t)(i + 0) * BSZ + (j + 1)] = s01 > 0.f ? sqrtf(s01) : 0.f;
    g_dist[(size_t)(i + 1) * BSZ + (j + 0)] = s10 > 0.f ? sqrtf(s10) : 0.f;
    g_dist[(size_t)(i + 1) * BSZ + (j + 1)] = s11 > 0.f ? sqrtf(s11) : 0.f;
}

// ---------------------------------------------------------------------------
// Kernel 2: warp-per-pair mining + fused deterministic finalize.
// Per pair (i, p, c):
//   j_min = first j: neg[j] && d_ap < d[i,j] < d_ap+margin
//   found  -> dan = d[i, negrank(j_min)]   (reference quirk: neg-rank index)
//   !found -> dan = d[i, j0(c)]
//   value  = relu(d_ap^2 - dan^2 + margin)
// Row lives in registers (lane l owns js 4(l+32k)+e); dan via uniform shuffle.
// ---------------------------------------------------------------------------
__global__ __launch_bounds__(256, 4)
void mine_kernel(float* __restrict__ out) {
    __shared__ unsigned negwS[NCLS * 16];
    __shared__ int      nrkbS[NCLS * 16];
    __shared__ int      j0S[NCLS];
    __shared__ float    rs[256];
    __shared__ int      sLast;

    const int tid  = threadIdx.x;
    const int warp = tid >> 5;
    const int lane = tid & 31;

    #pragma unroll
    for (int k = 0; k < 4; k++) {
        negwS[tid + 256 * k] = g_negw[tid + 256 * k];
        nrkbS[tid + 256 * k] = g_nrkb[tid + 256 * k];
    }
    if (tid < NCLS) j0S[tid] = g_j0[tid];
    const int np = g_npairs;
    __syncthreads();

    for (unsigned idx = blockIdx.x * 8 + warp; idx < (unsigned)np;
         idx += MBLK * 8) {
        const unsigned pr = __ldg(&g_pairs[idx]);
        const int i = pr & 511;
        const int p = (pr >> 9) & 511;
        const int c = pr >> 18;

        const float*  rowb = g_dist + (size_t)i * BSZ;
        const float4* row4 = (const float4*)rowb;
        const float4 rv0 = __ldg(row4 + lane);
        const float4 rv1 = __ldg(row4 + lane + 32);
        const float4 rv2 = __ldg(row4 + lane + 64);
        const float4 rv3 = __ldg(row4 + lane + 96);
        const float dap = __ldg(rowb + p);
        const float hi  = dap + MARGIN;

        const int wb = lane >> 3;
        const unsigned mw0 = negwS[c * 16 + wb + 0];
        const unsigned mw1 = negwS[c * 16 + wb + 4];
        const unsigned mw2 = negwS[c * 16 + wb + 8];
        const unsigned mw3 = negwS[c * 16 + wb + 12];

        // per-lane smallest hit: iterate j DESCENDING, overwrite on hit
        unsigned cand = 1024;
#define CHK(K, E, DV, MW)                                                   \
        {                                                                   \
            const unsigned bit = (unsigned)((4 * lane + (E)) & 31);         \
            if (((MW >> bit) & 1u) && (DV) > dap && (DV) < hi)              \
                cand = (unsigned)(4 * (lane + 32 * (K)) + (E));             \
        }
        CHK(3, 3, rv3.w, mw3) CHK(3, 2, rv3.z, mw3)
        CHK(3, 1, rv3.y, mw3) CHK(3, 0, rv3.x, mw3)
        CHK(2, 3, rv2.w, mw2) CHK(2, 2, rv2.z, mw2)
        CHK(2, 1, rv2.y, mw2) CHK(2, 0, rv2.x, mw2)
        CHK(1, 3, rv1.w, mw1) CHK(1, 2, rv1.z, mw1)
        CHK(1, 1, rv1.y, mw1) CHK(1, 0, rv1.x, mw1)
        CHK(0, 3, rv0.w, mw0) CHK(0, 2, rv0.z, mw0)
        CHK(0, 1, rv0.y, mw0) CHK(0, 0, rv0.x, mw0)
#undef CHK

        const unsigned jmin = __reduce_min_sync(0xffffffffu, cand);

        int di;                                // dan column (warp-uniform)
        if (jmin < 1024u) {
            const int q = jmin >> 5, bit = jmin & 31;
            di = nrkbS[c * 16 + q] +
                 __popc(negwS[c * 16 + q] & ((1u << bit) - 1u));
        } else {
            di = j0S[c];
        }

        // fetch row[di] from the distributed registers (di uniform)
        const int f4 = di >> 2, src = f4 & 31, kk = f4 >> 5, e = di & 3;
        const float4 fv = (kk == 0) ? rv0 : (kk == 1) ? rv1
                         : (kk == 2) ? rv2 : rv3;
        const float vsel = (e == 0) ? fv.x : (e == 1) ? fv.y
                          : (e == 2) ? fv.z : fv.w;
        const float dan = __shfl_sync(0xffffffffu, vsel, src);

        const float v = fmaf(dap, dap, MARGIN) - dan * dan;
        if (lane == 0) g_pairval[idx] = v > 0.f ? v : 0.f;
    }

    __threadfence();
    __syncthreads();
    if (tid == 0) sLast = (atomicAdd(&g_ctr, 1) == MBLK - 1) ? 1 : 0;
    __syncthreads();

    // last block: deterministic fixed-order final reduction over np values
    if (sLast) {
        __threadfence();
        float acc = 0.f;
        for (int s = tid; s < np; s += 256) acc += g_pairval[s];
        rs[tid] = acc;
        __syncthreads();
        #pragma unroll
        for (int s = 128; s > 0; s >>= 1) {
            if (tid < s) rs[tid] += rs[tid + s];
            __syncthreads();
        }
        if (tid == 0) {
            out[0] = rs[0] / (float)np;
            g_ctr  = 0;                        // reset for next graph replay
        }
    }
}

// ---------------------------------------------------------------------------
extern "C" void kernel_launch(void* const* d_in, const int* in_sizes, int n_in,
                              void* d_out, int out_size) {
    const float* emb    = (const float*)d_in[0];
    const int*   labels = (const int*)d_in[1];
    float*       out    = (float*)d_out;

    dist_pre_kernel<<<257, 256>>>(emb, labels);
    mine_kernel<<<MBLK, 256>>>(out);
}

// round 16
// speedup vs baseline: 2.4882x; 1.0194x over previous
#include <cuda_runtime.h>
#include <cuda_bf16.h>
#include <cstdint>

#define BSZ 512
#define DIM 128
#define NCLS 64
#define MARGIN 0.2f
#define PAIR_CAP 131072
#define NBLK 257               // 256 dist tiles + 1 table block

// Scratch (no allocations anywhere)
__device__ float    g_dist[BSZ * BSZ];
__device__ unsigned g_negw[NCLS * 16];
__device__ int      g_nrkb[NCLS * 16];
__device__ int      g_j0[NCLS];
__device__ int      g_npairs;
__device__ unsigned g_pairs[PAIR_CAP];     // packed (i | p<<9 | c<<18)
__device__ float    g_pairval[PAIR_CAP];
__device__ int      g_bar;                 // phase barrier counter (reset at end)
__device__ int      g_ctr;                 // finalize counter     (reset at end)

typedef unsigned long long ull;

// ---- packed f32x2 helpers (Blackwell) -------------------------------------
__device__ __forceinline__ ull add2(ull a, ull b) {
    ull r; asm("add.rn.f32x2 %0, %1, %2;" : "=l"(r) : "l"(a), "l"(b)); return r;
}
__device__ __forceinline__ ull fma2(ull a, ull b, ull c) {
    ull r; asm("fma.rn.f32x2 %0, %1, %2, %3;" : "=l"(r) : "l"(a), "l"(b), "l"(c)); return r;
}
__device__ __forceinline__ float sum2(ull v) {
    float lo, hi;
    asm("mov.b64 {%0, %1}, %2;" : "=f"(lo), "=f"(hi) : "l"(v));
    return lo + hi;
}
__device__ __forceinline__ int ld_vol(int* p) {
    int v; asm volatile("ld.volatile.global.s32 %0, [%1];" : "=r"(v) : "l"(p));
    return v;
}

// ---------------------------------------------------------------------------
// ONE persistent kernel, single wave (257 blocks <= resident capacity).
//  Phase A: blocks 0..255 compute the 32x32-tiled f32x2 distance matrix;
//           block 256 builds label tables + packed pair list concurrently.
//  Grid spin barrier (atomic arrive + volatile poll).
//  Phase B: warp-per-pair mining (row in registers, descending-overwrite
//           window scan, reduce_min; neg-rank via smem tables).
//  Finalize: atomic-counter last block, fixed-order; resets counters.
// ---------------------------------------------------------------------------
__global__ __launch_bounds__(256, 1)
void fused_kernel(const float* __restrict__ emb,
                  const int* __restrict__ labels,
                  float* __restrict__ out) {
    __shared__ float sA[32][130];     // phase A scratch / phase B tables
    __shared__ float sB[32][130];
    __shared__ int   sNp, sLast;

    const int tid  = threadIdx.x;
    const int warp = tid >> 5;
    const int lane = tid & 31;
    const int bx   = blockIdx.x;

    // ======================= PHASE A =======================
    if (bx == 256) {
        // ---- table block: label-only precompute ----
        int*      slab     = (int*)sB;              // 512
        unsigned* sNegw    = (unsigned*)sB + 512;   // 1024
        int*      kcount   = (int*)sA;              // 64
        int*      membase  = kcount + 64;           // 64
        int*      pairbase = membase + 64;          // 64
        int*      sMlist   = pairbase + 64;         // 512

        slab[tid]       = labels[tid];
        slab[tid + 256] = labels[tid + 256];
        __syncthreads();

        #pragma unroll
        for (int mi = 0; mi < 4; mi++) {
            const int m = tid * 4 + mi;
            const int c = m >> 4, q = m & 15;
            unsigned bits = 0;
            for (int l0 = 0; l0 < 32; l0++) {
                const int l = (l0 + tid) & 31;
                if (slab[q * 32 + l] == c) bits |= 1u << l;
            }
            sNegw[m]  = ~bits;
            g_negw[m] = ~bits;
        }
        __syncthreads();

        if (tid < NCLS) {
            const int c = tid;
            int nb = 0, kc = 0, j0v = 0, f = 0;
            #pragma unroll
            for (int q = 0; q < 16; q++) {
                const unsigned nw = sNegw[c * 16 + q];
                g_nrkb[c * 16 + q] = nb;
                nb += __popc(nw);
                kc += __popc(~nw);
                if (!f && nw) { j0v = q * 32 + __ffs(nw) - 1; f = 1; }
            }
            kcount[c] = kc;
            g_j0[c]   = j0v;              // argmax(all-false) == 0
        }
        __syncthreads();

        if (tid == 0) {
            int mb = 0, pb = 0;
            for (int c = 0; c < NCLS; c++) {
                membase[c]  = mb;
                pairbase[c] = pb;
                mb += kcount[c];
                pb += kcount[c] * (kcount[c] - 1) / 2;
            }
            g_npairs = pb;
        }
        __syncthreads();

        if (tid < NCLS) {
            const int c = tid;
            int mb = membase[c];
            #pragma unroll
            for (int q = 0; q < 16; q++) {
                unsigned mt = ~sNegw[c * 16 + q];
                while (mt) {
                    const int b = __ffs(mt) - 1;
                    mt &= mt - 1;
                    sMlist[mb++] = q * 32 + b;
                }
            }
            const int k = kcount[c], s = membase[c];
            int off = pairbase[c];
            for (int a2 = 0; a2 < k; a2++) {
                const unsigned iv = (unsigned)sMlist[s + a2];
                for (int b2 = a2 + 1; b2 < k; b2++)
                    g_pairs[off++] = iv | ((unsigned)sMlist[s + b2] << 9)
                                        | ((unsigned)c << 18);
            }
        }
    } else {
        // ---- dist tile: 32x32, 2x2 micro, packed f32x2 ----
        const int tx = tid & 15, ty = tid >> 4;
        const int i0 = (bx >> 4) * 32;
        const int j0 = (bx & 15) * 32;

        #pragma unroll
        for (int t = tid; t < 1024; t += 256) {
            const int row = t >> 5;
            const int c4  = t & 31;
            const float4 va = *(const float4*)(emb + (size_t)(i0 + row) * DIM + c4 * 4);
            float2* da = (float2*)&sA[row][c4 * 4];
            da[0] = make_float2(va.x, va.y);
            da[1] = make_float2(va.z, va.w);
            const float4 vb = *(const float4*)(emb + (size_t)(j0 + row) * DIM + c4 * 4);
            float2* db = (float2*)&sB[row][c4 * 4];
            db[0] = make_float2(-vb.x, -vb.y);
            db[1] = make_float2(-vb.z, -vb.w);
        }
        __syncthreads();

        const ull* A0 = (const ull*)sA[ty * 2 + 0];
        const ull* A1 = (const ull*)sA[ty * 2 + 1];
        const ull* B0 = (const ull*)sB[tx * 2 + 0];
        const ull* B1 = (const ull*)sB[tx * 2 + 1];

        ull acc00 = 0ull, acc01 = 0ull, acc10 = 0ull, acc11 = 0ull;
        #pragma unroll 16
        for (int k2 = 0; k2 < 64; k2++) {
            const ull a0 = A0[k2];
            const ull a1 = A1[k2];
            const ull b0 = B0[k2];
            const ull b1 = B1[k2];
            ull t;
            t = add2(a0, b0); acc00 = fma2(t, t, acc00);
            t = add2(a0, b1); acc01 = fma2(t, t, acc01);
            t = add2(a1, b0); acc10 = fma2(t, t, acc10);
            t = add2(a1, b1); acc11 = fma2(t, t, acc11);
        }

        const int i = i0 + ty * 2;
        const int j = j0 + tx * 2;
        const float s00 = sum2(acc00), s01 = sum2(acc01);
        const float s10 = sum2(acc10), s11 = sum2(acc11);
        g_dist[(size_t)(i + 0) * BSZ + (j + 0)] = s00 > 0.f ? sqrtf(s00) : 0.f;
        g_dist[(size_t)(i + 0) * BSZ + (j + 1)] = s01 > 0.f ? sqrtf(s01) : 0.f;
        g_dist[(size_t)(i + 1) * BSZ + (j + 0)] = s10 > 0.f ? sqrtf(s10) : 0.f;
        g_dist[(size_t)(i + 1) * BSZ + (j + 1)] = s11 > 0.f ? sqrtf(s11) : 0.f;
    }

    // ======================= GRID BARRIER =======================
    __threadfence();
    __syncthreads();
    if (tid == 0) {
        atomicAdd(&g_bar, 1);
        while (ld_vol(&g_bar) < NBLK) __nanosleep(32);
    }
    __syncthreads();
    __threadfence();

    // ======================= PHASE B: mining =======================
    unsigned* negwS = (unsigned*)&sA[0][0];          // 1024
    int*      nrkbS = (int*)&sA[0][0] + 1024;        // 1024
    int*      j0S   = (int*)&sA[0][0] + 2048;        // 64
    float*    rs    = (float*)&sA[0][0] + 2112;      // 256

    #pragma unroll
    for (int k = 0; k < 4; k++) {
        negwS[tid + 256 * k] = g_negw[tid + 256 * k];
        nrkbS[tid + 256 * k] = g_nrkb[tid + 256 * k];
    }
    if (tid < NCLS) j0S[tid] = g_j0[tid];
    if (tid == 0)   sNp = ld_vol(&g_npairs);
    __syncthreads();
    const int np = sNp;

    for (unsigned idx = bx * 8 + warp; idx < (unsigned)np; idx += NBLK * 8) {
        const unsigned pr = __ldg(&g_pairs[idx]);
        const int i = pr & 511;
        const int p = (pr >> 9) & 511;
        const int c = pr >> 18;

        const float*  rowb = g_dist + (size_t)i * BSZ;
        const float4* row4 = (const float4*)rowb;
        const float4 rv0 = __ldg(row4 + lane);
        const float4 rv1 = __ldg(row4 + lane + 32);
        const float4 rv2 = __ldg(row4 + lane + 64);
        const float4 rv3 = __ldg(row4 + lane + 96);
        const float dap = __ldg(rowb + p);
        const float hi  = dap + MARGIN;

        const int wb = lane >> 3;
        const unsigned mw0 = negwS[c * 16 + wb + 0];
        const unsigned mw1 = negwS[c * 16 + wb + 4];
        const unsigned mw2 = negwS[c * 16 + wb + 8];
        const unsigned mw3 = negwS[c * 16 + wb + 12];

        // per-lane smallest hit: iterate j DESCENDING, overwrite on hit
        unsigned cand = 1024;
#define CHK(K, E, DV, MW)                                                   \
        {                                                                   \
            const unsigned bit = (unsigned)((4 * lane + (E)) & 31);         \
            if (((MW >> bit) & 1u) && (DV) > dap && (DV) < hi)              \
                cand = (unsigned)(4 * (lane + 32 * (K)) + (E));             \
        }
        CHK(3, 3, rv3.w, mw3) CHK(3, 2, rv3.z, mw3)
        CHK(3, 1, rv3.y, mw3) CHK(3, 0, rv3.x, mw3)
        CHK(2, 3, rv2.w, mw2) CHK(2, 2, rv2.z, mw2)
        CHK(2, 1, rv2.y, mw2) CHK(2, 0, rv2.x, mw2)
        CHK(1, 3, rv1.w, mw1) CHK(1, 2, rv1.z, mw1)
        CHK(1, 1, rv1.y, mw1) CHK(1, 0, rv1.x, mw1)
        CHK(0, 3, rv0.w, mw0) CHK(0, 2, rv0.z, mw0)
        CHK(0, 1, rv0.y, mw0) CHK(0, 0, rv0.x, mw0)
#undef CHK

        const unsigned jmin = __reduce_min_sync(0xffffffffu, cand);

        int di;                                // dan column (warp-uniform)
        if (jmin < 1024u) {
            const int q = jmin >> 5, bit = jmin & 31;
            di = nrkbS[c * 16 + q] +
                 __popc(negwS[c * 16 + q] & ((1u << bit) - 1u));
        } else {
            di = j0S[c];
        }

        // fetch row[di] from distributed registers (di warp-uniform)
        const int f4 = di >> 2, src = f4 & 31, kk = f4 >> 5, e = di & 3;
        const float4 fv = (kk == 0) ? rv0 : (kk == 1) ? rv1
                         : (kk == 2) ? rv2 : rv3;
        const float vsel = (e == 0) ? fv.x : (e == 1) ? fv.y
                          : (e == 2) ? fv.z : fv.w;
        const float dan = __shfl_sync(0xffffffffu, vsel, src);

        const float v = fmaf(dap, dap, MARGIN) - dan * dan;
        if (lane == 0) g_pairval[idx] = v > 0.f ? v : 0.f;
    }

    // ======================= FINALIZE =======================
    __threadfence();
    __syncthreads();
    if (tid == 0) sLast = (atomicAdd(&g_ctr, 1) == NBLK - 1) ? 1 : 0;
    __syncthreads();

    if (sLast) {
        __threadfence();
        float acc = 0.f;
        for (int s = tid; s < np; s += 256) acc += g_pairval[s];
        rs[tid] = acc;
        __syncthreads();
        #pragma unroll
        for (int s = 128; s > 0; s >>= 1) {
            if (tid < s) rs[tid] += rs[tid + s];
            __syncthreads();
        }
        if (tid == 0) {
            out[0] = rs[0] / (float)np;
            g_ctr = 0;                     // reset for next graph replay
            g_bar = 0;
        }
    }
}

// ---------------------------------------------------------------------------
extern "C" void kernel_launch(void* const* d_in, const int* in_sizes, int n_in,
                              void* d_out, int out_size) {
    const float* emb    = (const float*)d_in[0];
    const int*   labels = (const int*)d_in[1];
    float*       out    = (float*)d_out;

    fused_kernel<<<NBLK, 256>>>(emb, labels, out);
}

// round 17
// speedup vs baseline: 2.7473x; 1.1041x over previous
#include <cuda_runtime.h>
#include <cuda_bf16.h>
#include <cstdint>

#define BSZ 512
#define DIM 128
#define NCLS 64
#define MARGIN 0.2f
#define PAIR_CAP 131072
#define NTILE 136              // 16 diagonal + 120 upper-triangle tiles
#define NBLK  137              // + 1 table block

// Scratch (no allocations anywhere)
__device__ float    g_dist[BSZ * BSZ];
__device__ unsigned g_negw[NCLS * 16];
__device__ int      g_nrkb[NCLS * 16];
__device__ int      g_j0[NCLS];
__device__ int      g_npairs;
__device__ unsigned g_pairs[PAIR_CAP];     // packed (i | p<<9 | c<<18)
__device__ float    g_pairval[PAIR_CAP];
__device__ int      g_bar;                 // phase barrier counter (reset at end)
__device__ int      g_ctr;                 // finalize counter     (reset at end)

typedef unsigned long long ull;

// ---- packed f32x2 helpers (Blackwell) -------------------------------------
__device__ __forceinline__ ull add2(ull a, ull b) {
    ull r; asm("add.rn.f32x2 %0, %1, %2;" : "=l"(r) : "l"(a), "l"(b)); return r;
}
__device__ __forceinline__ ull fma2(ull a, ull b, ull c) {
    ull r; asm("fma.rn.f32x2 %0, %1, %2, %3;" : "=l"(r) : "l"(a), "l"(b), "l"(c)); return r;
}
__device__ __forceinline__ float sum2(ull v) {
    float lo, hi;
    asm("mov.b64 {%0, %1}, %2;" : "=f"(lo), "=f"(hi) : "l"(v));
    return lo + hi;
}
__device__ __forceinline__ int ld_vol(int* p) {
    int v; asm volatile("ld.volatile.global.s32 %0, [%1];" : "=r"(v) : "l"(p));
    return v;
}

// ---------------------------------------------------------------------------
// ONE persistent kernel, single wave (137 blocks, 1/SM).
//  Phase A: 136 blocks compute the UPPER-TRIANGLE 32x32 dist tiles (diff-based
//           f32x2, matching reference sum((a-b)^2)); off-diagonal tiles also
//           emit the transposed tile ((a-b)^2 == (b-a)^2 bitwise) staged
//           through smem for coalesced stores. Block 136 builds label tables
//           + packed pair list concurrently.
//  Grid spin barrier. Phase B: warp-per-pair mining. Finalize: last block.
// ---------------------------------------------------------------------------
__global__ __launch_bounds__(256, 1)
void fused_kernel(const float* __restrict__ emb,
                  const int* __restrict__ labels,
                  float* __restrict__ out) {
    __shared__ float sA[32][130];     // anchors / transpose staging / tables
    __shared__ float sB[32][130];
    __shared__ int   sNp, sLast;

    const int tid  = threadIdx.x;
    const int warp = tid >> 5;
    const int lane = tid & 31;
    const int bx   = blockIdx.x;

    // ======================= PHASE A =======================
    if (bx == NTILE) {
        // ---- table block: label-only precompute ----
        int*      slab     = (int*)sB;              // 512
        unsigned* sNegw    = (unsigned*)sB + 512;   // 1024
        int*      kcount   = (int*)sA;              // 64
        int*      membase  = kcount + 64;           // 64
        int*      pairbase = membase + 64;          // 64
        int*      sMlist   = pairbase + 64;         // 512

        slab[tid]       = labels[tid];
        slab[tid + 256] = labels[tid + 256];
        __syncthreads();

        #pragma unroll
        for (int mi = 0; mi < 4; mi++) {
            const int m = tid * 4 + mi;
            const int c = m >> 4, q = m & 15;
            unsigned bits = 0;
            for (int l0 = 0; l0 < 32; l0++) {
                const int l = (l0 + tid) & 31;
                if (slab[q * 32 + l] == c) bits |= 1u << l;
            }
            sNegw[m]  = ~bits;
            g_negw[m] = ~bits;
        }
        __syncthreads();

        if (tid < NCLS) {
            const int c = tid;
            int nb = 0, kc = 0, j0v = 0, f = 0;
            #pragma unroll
            for (int q = 0; q < 16; q++) {
                const unsigned nw = sNegw[c * 16 + q];
                g_nrkb[c * 16 + q] = nb;
                nb += __popc(nw);
                kc += __popc(~nw);
                if (!f && nw) { j0v = q * 32 + __ffs(nw) - 1; f = 1; }
            }
            kcount[c] = kc;
            g_j0[c]   = j0v;              // argmax(all-false) == 0
        }
        __syncthreads();

        if (tid == 0) {
            int mb = 0, pb = 0;
            for (int c = 0; c < NCLS; c++) {
                membase[c]  = mb;
                pairbase[c] = pb;
                mb += kcount[c];
                pb += kcount[c] * (kcount[c] - 1) / 2;
            }
            g_npairs = pb;
        }
        __syncthreads();

        if (tid < NCLS) {
            const int c = tid;
            int mb = membase[c];
            #pragma unroll
            for (int q = 0; q < 16; q++) {
                unsigned mt = ~sNegw[c * 16 + q];
                while (mt) {
                    const int b = __ffs(mt) - 1;
                    mt &= mt - 1;
                    sMlist[mb++] = q * 32 + b;
                }
            }
            const int k = kcount[c], s = membase[c];
            int off = pairbase[c];
            for (int a2 = 0; a2 < k; a2++) {
                const unsigned iv = (unsigned)sMlist[s + a2];
                for (int b2 = a2 + 1; b2 < k; b2++)
                    g_pairs[off++] = iv | ((unsigned)sMlist[s + b2] << 9)
                                        | ((unsigned)c << 18);
            }
        }
    } else {
        // ---- triangle tile: unrank bx -> (ti, tj), ti <= tj ----
        int ti = 0, rem = bx;
        while (rem >= 16 - ti) { rem -= 16 - ti; ti++; }
        const int tj = ti + rem;
        const int i0 = ti * 32;
        const int j0 = tj * 32;

        const int tx = tid & 15, ty = tid >> 4;

        #pragma unroll
        for (int t = tid; t < 1024; t += 256) {
            const int row = t >> 5;
            const int c4  = t & 31;
            const float4 va = *(const float4*)(emb + (size_t)(i0 + row) * DIM + c4 * 4);
            float2* da = (float2*)&sA[row][c4 * 4];
            da[0] = make_float2(va.x, va.y);
            da[1] = make_float2(va.z, va.w);
            const float4 vb = *(const float4*)(emb + (size_t)(j0 + row) * DIM + c4 * 4);
            float2* db = (float2*)&sB[row][c4 * 4];
            db[0] = make_float2(-vb.x, -vb.y);
            db[1] = make_float2(-vb.z, -vb.w);
        }
        __syncthreads();

        const ull* A0 = (const ull*)sA[ty * 2 + 0];
        const ull* A1 = (const ull*)sA[ty * 2 + 1];
        const ull* B0 = (const ull*)sB[tx * 2 + 0];
        const ull* B1 = (const ull*)sB[tx * 2 + 1];

        ull acc00 = 0ull, acc01 = 0ull, acc10 = 0ull, acc11 = 0ull;
        #pragma unroll 16
        for (int k2 = 0; k2 < 64; k2++) {
            const ull a0 = A0[k2];
            const ull a1 = A1[k2];
            const ull b0 = B0[k2];
            const ull b1 = B1[k2];
            ull t;
            t = add2(a0, b0); acc00 = fma2(t, t, acc00);
            t = add2(a0, b1); acc01 = fma2(t, t, acc01);
            t = add2(a1, b0); acc10 = fma2(t, t, acc10);
            t = add2(a1, b1); acc11 = fma2(t, t, acc11);
        }

        const int i = i0 + ty * 2;
        const int j = j0 + tx * 2;
        const float s00 = sum2(acc00) ;
        const float s01 = sum2(acc01);
        const float s10 = sum2(acc10);
        const float s11 = sum2(acc11);
        const float d00 = s00 > 0.f ? sqrtf(s00) : 0.f;
        const float d01 = s01 > 0.f ? sqrtf(s01) : 0.f;
        const float d10 = s10 > 0.f ? sqrtf(s10) : 0.f;
        const float d11 = s11 > 0.f ? sqrtf(s11) : 0.f;
        g_dist[(size_t)(i + 0) * BSZ + (j + 0)] = d00;
        g_dist[(size_t)(i + 0) * BSZ + (j + 1)] = d01;
        g_dist[(size_t)(i + 1) * BSZ + (j + 0)] = d10;
        g_dist[(size_t)(i + 1) * BSZ + (j + 1)] = d11;

        if (ti != tj) {
            // transposed tile via smem staging (coalesced stores)
            __syncthreads();                 // done reading sA/sB
            const int li = ty * 2, lj = tx * 2;    // local indices
            sA[lj + 0][li + 0] = d00;        // sA[t_row=j_local][t_col=i_local]
            sA[lj + 1][li + 0] = d01;
            sA[lj + 0][li + 1] = d10;
            sA[lj + 1][li + 1] = d11;
            __syncthreads();
            #pragma unroll
            for (int t = tid; t < 1024; t += 256) {
                const int row = t >> 5;      // local j
                const int col = t & 31;      // local i
                g_dist[(size_t)(j0 + row) * BSZ + (i0 + col)] = sA[row][col];
            }
        }
    }

    // ======================= GRID BARRIER =======================
    __threadfence();
    __syncthreads();
    if (tid == 0) {
        atomicAdd(&g_bar, 1);
        while (ld_vol(&g_bar) < NBLK) __nanosleep(32);
    }
    __syncthreads();
    __threadfence();

    // ======================= PHASE B: mining =======================
    unsigned* negwS = (unsigned*)&sA[0][0];          // 1024
    int*      nrkbS = (int*)&sA[0][0] + 1024;        // 1024
    int*      j0S   = (int*)&sA[0][0] + 2048;        // 64
    float*    rs    = (float*)&sA[0][0] + 2112;      // 256

    #pragma unroll
    for (int k = 0; k < 4; k++) {
        negwS[tid + 256 * k] = g_negw[tid + 256 * k];
        nrkbS[tid + 256 * k] = g_nrkb[tid + 256 * k];
    }
    if (tid < NCLS) j0S[tid] = g_j0[tid];
    if (tid == 0)   sNp = ld_vol(&g_npairs);
    __syncthreads();
    const int np = sNp;

    for (unsigned idx = bx * 8 + warp; idx < (unsigned)np; idx += NBLK * 8) {
        const unsigned pr = __ldg(&g_pairs[idx]);
        const int i = pr & 511;
        const int p = (pr >> 9) & 511;
        const int c = pr >> 18;

        const float*  rowb = g_dist + (size_t)i * BSZ;
        const float4* row4 = (const float4*)rowb;
        const float4 rv0 = __ldg(row4 + lane);
        const float4 rv1 = __ldg(row4 + lane + 32);
        const float4 rv2 = __ldg(row4 + lane + 64);
        const float4 rv3 = __ldg(row4 + lane + 96);
        const float dap = __ldg(rowb + p);
        const float hi  = dap + MARGIN;

        const int wb = lane >> 3;
        const unsigned mw0 = negwS[c * 16 + wb + 0];
        const unsigned mw1 = negwS[c * 16 + wb + 4];
        const unsigned mw2 = negwS[c * 16 + wb + 8];
        const unsigned mw3 = negwS[c * 16 + wb + 12];

        // per-lane smallest hit: iterate j DESCENDING, overwrite on hit
        unsigned cand = 1024;
#define CHK(K, E, DV, MW)                                                   \
        {                                                                   \
            const unsigned bit = (unsigned)((4 * lane + (E)) & 31);         \
            if (((MW >> bit) & 1u) && (DV) > dap && (DV) < hi)              \
                cand = (unsigned)(4 * (lane + 32 * (K)) + (E));             \
        }
        CHK(3, 3, rv3.w, mw3) CHK(3, 2, rv3.z, mw3)
        CHK(3, 1, rv3.y, mw3) CHK(3, 0, rv3.x, mw3)
        CHK(2, 3, rv2.w, mw2) CHK(2, 2, rv2.z, mw2)
        CHK(2, 1, rv2.y, mw2) CHK(2, 0, rv2.x, mw2)
        CHK(1, 3, rv1.w, mw1) CHK(1, 2, rv1.z, mw1)
        CHK(1, 1, rv1.y, mw1) CHK(1, 0, rv1.x, mw1)
        CHK(0, 3, rv0.w, mw0) CHK(0, 2, rv0.z, mw0)
        CHK(0, 1, rv0.y, mw0) CHK(0, 0, rv0.x, mw0)
#undef CHK

        const unsigned jmin = __reduce_min_sync(0xffffffffu, cand);

        int di;                                // dan column (warp-uniform)
        if (jmin < 1024u) {
            const int q = jmin >> 5, bit = jmin & 31;
            di = nrkbS[c * 16 + q] +
                 __popc(negwS[c * 16 + q] & ((1u << bit) - 1u));
        } else {
            di = j0S[c];
        }

        // fetch row[di] from distributed registers (di warp-uniform)
        const int f4 = di >> 2, src = f4 & 31, kk = f4 >> 5, e = di & 3;
        const float4 fv = (kk == 0) ? rv0 : (kk == 1) ? rv1
                         : (kk == 2) ? rv2 : rv3;
        const float vsel = (e == 0) ? fv.x : (e == 1) ? fv.y
                          : (e == 2) ? fv.z : fv.w;
        const float dan = __shfl_sync(0xffffffffu, vsel, src);

        const float v = fmaf(dap, dap, MARGIN) - dan * dan;
        if (lane == 0) g_pairval[idx] = v > 0.f ? v : 0.f;
    }

    // ======================= FINALIZE =======================
    __threadfence();
    __syncthreads();
    if (tid == 0) sLast = (atomicAdd(&g_ctr, 1) == NBLK - 1) ? 1 : 0;
    __syncthreads();

    if (sLast) {
        __threadfence();
        float acc = 0.f;
        for (int s = tid; s < np; s += 256) acc += g_pairval[s];
        rs[tid] = acc;
        __syncthreads();
        #pragma unroll
        for (int s = 128; s > 0; s >>= 1) {
            if (tid < s) rs[tid] += rs[tid + s];
            __syncthreads();
        }
        if (tid == 0) {
            out[0] = rs[0] / (float)np;
            g_ctr = 0;                     // reset for next graph replay
            g_bar = 0;
        }
    }
}

// ---------------------------------------------------------------------------
extern "C" void kernel_launch(void* const* d_in, const int* in_sizes, int n_in,
                              void* d_out, int out_size) {
    const float* emb    = (const float*)d_in[0];
    const int*   labels = (const int*)d_in[1];
    float*       out    = (float*)d_out;

    fused_kernel<<<NBLK, 256>>>(emb, labels, out);
}